// round 14
// baseline (speedup 1.0000x reference)
#include <cuda_runtime.h>
#include <cuda_fp16.h>
#include <cstdint>

// Shapes: x[4,1024,4096] f32, qweight[512,11008] i32 (8x4b along K),
// qzeros[32,1376] i32 (8x4b along N), scales[32,11008] f32, out[4096,11008] f32.
#define MDIM 4096
#define KDIM 4096
#define NDIM 11008

#define BM 128
#define BN 256
#define BK 64
#define STAGES 3
#define THREADS 512
#define NIT (KDIM / BK)          // 64
#define GRID_M (MDIM / BM)       // 32
#define GRID_N (NDIM / BN)       // 43

#define ROWB 128                                  // 128B rows, XOR swizzle
#define A_STAGE (BM * ROWB)                       // 16384
#define B_STAGE (BN * ROWB)                       // 32768
#define STAGE_BYTES (A_STAGE + B_STAGE)           // 49152
#define SMEM_TOTAL (STAGE_BYTES * STAGES)         // 147456 -> 1 CTA/SM (512 thr)

#define CVT_BLOCKS (MDIM * KDIM / 8 / 256)        // 8192
#define DQ_BX (NDIM / 64)                         // 172
#define DQ_BY (KDIM / 64)                         // 64
#define PREP_BLOCKS (CVT_BLOCKS + DQ_BX * DQ_BY)  // 19200

// fp16 staging of A (x) and dequantized W^T (N-major, K contiguous)
__device__ __align__(16) __half g_xh[(size_t)MDIM * KDIM];   // 33.5 MB
__device__ __align__(16) __half g_wt[(size_t)NDIM * KDIM];   // 90.2 MB

// ---------------- merged prepass: x->fp16  +  dequant/transpose ----------------
__global__ void __launch_bounds__(256) prep_kernel(const float* __restrict__ x,
                                                   const int* __restrict__ qweight,
                                                   const int* __restrict__ qzeros,
                                                   const float* __restrict__ scales) {
    const int t = threadIdx.x;
    if (blockIdx.x < CVT_BLOCKS) {
        size_t idx = (size_t)blockIdx.x * 256 + t;
        const float4* xp = reinterpret_cast<const float4*>(x) + idx * 2;
        float4 a = xp[0], b = xp[1];
        __half2 h0 = __floats2half2_rn(a.x, a.y);
        __half2 h1 = __floats2half2_rn(a.z, a.w);
        __half2 h2 = __floats2half2_rn(b.x, b.y);
        __half2 h3 = __floats2half2_rn(b.z, b.w);
        uint4 o;
        o.x = *reinterpret_cast<uint32_t*>(&h0);
        o.y = *reinterpret_cast<uint32_t*>(&h1);
        o.z = *reinterpret_cast<uint32_t*>(&h2);
        o.w = *reinterpret_cast<uint32_t*>(&h3);
        reinterpret_cast<uint4*>(g_xh)[idx] = o;   // normal writeback: stays L2-resident
        return;
    }
    __shared__ __align__(16) uint8_t tile[64 * 128];
    const int b = blockIdx.x - CVT_BLOCKS;
    const int n0 = (b % DQ_BX) * 64;
    const int by = b / DQ_BX;
    const int k0 = by * 64;
    const int kp0 = by * 8;
    const int g = k0 >> 7;

    const int nl = t & 63;
    const int n = n0 + nl;
    const int z = ((uint32_t)qzeros[g * (NDIM / 8) + (n >> 3)] >> ((n & 7) * 4)) & 0xF;
    const float s = scales[(size_t)g * NDIM + n];

    #pragma unroll
    for (int i = 0; i < 2; ++i) {
        int item = i * 256 + t;
        int kp = item >> 6;
        uint32_t q = (uint32_t)qweight[(size_t)(kp0 + kp) * NDIM + n];
        __half h[8];
        #pragma unroll
        for (int j = 0; j < 8; ++j) {
            int v = (q >> (4 * j)) & 0xF;
            h[j] = __float2half_rn((float)(v - z) * s);
        }
        int colb = (kp * 16) ^ ((nl & 7) << 4);
        *reinterpret_cast<uint4*>(tile + nl * 128 + colb) = *reinterpret_cast<uint4*>(h);
    }
    __syncthreads();
    #pragma unroll
    for (int i = 0; i < 8; ++i) {
        int idx = i * 256 + t;
        int row = idx >> 5, col = idx & 31;
        uint32_t v = *reinterpret_cast<uint32_t*>(tile + row * 128 + ((col * 4) ^ ((row & 7) << 4)));
        *reinterpret_cast<uint32_t*>(&g_wt[(size_t)(n0 + row) * KDIM + k0 + col * 2]) = v;
    }
}

// ---------------- PTX helpers ----------------
__device__ __forceinline__ void ldsm4(uint32_t* r, uint32_t addr) {
    asm volatile("ldmatrix.sync.aligned.m8n8.x4.shared.b16 {%0,%1,%2,%3}, [%4];"
                 : "=r"(r[0]), "=r"(r[1]), "=r"(r[2]), "=r"(r[3]) : "r"(addr));
}
__device__ __forceinline__ void mma16816(float* c, const uint32_t* a, uint32_t b0, uint32_t b1) {
    asm volatile("mma.sync.aligned.m16n8k16.row.col.f32.f16.f16.f32 "
                 "{%0,%1,%2,%3}, {%4,%5,%6,%7}, {%8,%9}, {%0,%1,%2,%3};"
                 : "+f"(c[0]), "+f"(c[1]), "+f"(c[2]), "+f"(c[3])
                 : "r"(a[0]), "r"(a[1]), "r"(a[2]), "r"(a[3]), "r"(b0), "r"(b1));
}
__device__ __forceinline__ void cp_async16(uint32_t dst, const void* src) {
    asm volatile("cp.async.cg.shared.global [%0], [%1], 16;" :: "r"(dst), "l"(src));
}
#define CP_COMMIT() asm volatile("cp.async.commit_group;" ::: "memory")
#define CP_WAIT(N)  asm volatile("cp.async.wait_group %0;" :: "n"(N) : "memory")

// ---------------- main GEMM: 128x256 tile, 512 threads, 1 CTA/SM ----------------
__global__ void __launch_bounds__(THREADS, 1) gemm_kernel(float* __restrict__ out) {
    extern __shared__ __align__(16) char smem[];
    const uint32_t smem_base = (uint32_t)__cvta_generic_to_shared(smem);

    const int t = threadIdx.x;
    const int wid = t >> 5;
    const int lane = t & 31;

    const int mtile = blockIdx.x & 31;          // mtile fastest: wave shares A fully + B slices in L2
    const int ntile = blockIdx.x >> 5;
    const int m0 = mtile * BM;
    const int n0 = ntile * BN;

    const int warp_m = wid & 3;                 // 4 slabs x 32 rows
    const int warp_n = wid >> 2;                // 4 slabs x 64 cols

    float acc[2][8][4];
    #pragma unroll
    for (int i = 0; i < 2; ++i)
        #pragma unroll
        for (int j = 0; j < 8; ++j)
            #pragma unroll
            for (int k = 0; k < 4; ++k) acc[i][j][k] = 0.f;

    // per-thread cp.async source/dest components
    const int ldRow = t >> 3;                   // 0..63 (row block step 64)
    const int ldCol = t & 7;                    // 16B chunk
    const uint32_t ldDstOff = ldRow * ROWB + ((ldCol * 16) ^ ((ldRow & 7) << 4));

    // rolling global source pointers (advance by BK per iter; issue targets it+2)
    const __half* srcA = g_xh + (size_t)(m0 + ldRow) * KDIM + ldCol * 8;
    const __half* srcB = g_wt + (size_t)(n0 + ldRow) * KDIM + ldCol * 8;

    auto issue_A = [&](uint32_t dstBase, const __half* src) {   // 128 rows: 2 blocks of 64
        #pragma unroll
        for (int j = 0; j < 2; ++j)
            cp_async16(dstBase + j * 64 * ROWB, src + (size_t)(j * 64) * KDIM);
    };
    auto issue_B = [&](uint32_t dstBase, const __half* src) {   // 256 rows: 4 blocks of 64
        #pragma unroll
        for (int j = 0; j < 4; ++j)
            cp_async16(dstBase + A_STAGE + j * 64 * ROWB, src + (size_t)(j * 64) * KDIM);
    };

    // prologue: stages 0 and 1 in flight
    issue_A(smem_base + ldDstOff, srcA);
    issue_B(smem_base + ldDstOff, srcB);
    CP_COMMIT();
    issue_A(smem_base + STAGE_BYTES + ldDstOff, srcA + BK);
    issue_B(smem_base + STAGE_BYTES + ldDstOff, srcB + BK);
    CP_COMMIT();
    srcA += 2 * BK;                              // now points at it+2 source
    srcB += 2 * BK;
    CP_WAIT(1);
    __syncthreads();

    const int rA = lane & 15;
    const int cA = (lane >> 4) * 16;
    const int swzA = (lane & 7) << 4;
    const int rB = ((lane >> 3) & 1) * 8 + (lane & 7);
    const int cB = (lane >> 4) * 16;
    const int swzB = (lane & 7) << 4;

    // warp-level smem row bases (stage-invariant parts)
    const uint32_t aRow0 = (warp_m * 32 + rA) * ROWB;
    const uint32_t bRow0 = (warp_n * 64 + rB) * ROWB;

    uint32_t afrag[2][2][4];     // double-buffered across kh
    uint32_t bfrag[2][2][4];     // slot0: np={0,1}, slot1: np={2,3}

    uint32_t consBase = smem_base;               // stage being consumed
    uint32_t prodBase = smem_base + 2 * STAGE_BYTES;   // stage being filled (it+2)

    #pragma unroll 1
    for (int it = 0; it < NIT; ++it) {
        const uint32_t aBase = consBase;
        const uint32_t bBase = consBase + A_STAGE;
        const bool more = (it + 2 < NIT);

        // preload kh=0: A frags + B slot0 (np 0,1)
        #pragma unroll
        for (int mi = 0; mi < 2; ++mi)
            ldsm4(afrag[0][mi], aBase + aRow0 + mi * 16 * ROWB + (cA ^ swzA));
        #pragma unroll
        for (int np = 0; np < 2; ++np)
            ldsm4(bfrag[0][np], bBase + bRow0 + np * 16 * ROWB + (cB ^ swzB));

        #pragma unroll
        for (int kh = 0; kh < 4; ++kh) {
            const int cur = kh & 1, nxt = cur ^ 1;
            const uint32_t kcol = kh * 32;

            // B slot1 (np 2,3) for this kh
            #pragma unroll
            for (int np = 0; np < 2; ++np)
                ldsm4(bfrag[1][np], bBase + bRow0 + (np + 2) * 16 * ROWB + ((kcol + cB) ^ swzB));
            // A frags for kh+1
            if (kh < 3) {
                #pragma unroll
                for (int mi = 0; mi < 2; ++mi)
                    ldsm4(afrag[nxt][mi], aBase + aRow0 + mi * 16 * ROWB + ((kcol + 32 + cA) ^ swzA));
            }
            // interleave next-next stage global loads into MMA-rich region
            if (kh == 0 && more) issue_A(prodBase + ldDstOff, srcA);
            if (kh == 1) { if (more) issue_B(prodBase + ldDstOff, srcB); CP_COMMIT(); }

            // MMA pair 0 (np 0,1)
            #pragma unroll
            for (int np = 0; np < 2; ++np)
                #pragma unroll
                for (int mi = 0; mi < 2; ++mi) {
                    mma16816(acc[mi][2 * np],     afrag[cur][mi], bfrag[0][np][0], bfrag[0][np][2]);
                    mma16816(acc[mi][2 * np + 1], afrag[cur][mi], bfrag[0][np][1], bfrag[0][np][3]);
                }
            // B slot0 (np 0,1) for kh+1, hidden under pair-1 MMAs
            if (kh < 3) {
                #pragma unroll
                for (int np = 0; np < 2; ++np)
                    ldsm4(bfrag[0][np], bBase + bRow0 + np * 16 * ROWB + ((kcol + 32 + cB) ^ swzB));
            }
            // MMA pair 1 (np 2,3)
            #pragma unroll
            for (int np = 0; np < 2; ++np)
                #pragma unroll
                for (int mi = 0; mi < 2; ++mi) {
                    mma16816(acc[mi][4 + 2 * np],     afrag[cur][mi], bfrag[1][np][0], bfrag[1][np][2]);
                    mma16816(acc[mi][4 + 2 * np + 1], afrag[cur][mi], bfrag[1][np][1], bfrag[1][np][3]);
                }
        }

        // rotate stages, advance sources
        consBase += STAGE_BYTES;
        if (consBase == smem_base + 3 * STAGE_BYTES) consBase = smem_base;
        prodBase += STAGE_BYTES;
        if (prodBase == smem_base + 3 * STAGE_BYTES) prodBase = smem_base;
        srcA += BK;
        srcB += BK;

        // wait for stage it+1 (committed last iter) before next iter reads it
        CP_WAIT(1);
        __syncthreads();
    }

    // ---- epilogue: streaming float2 stores (out is never re-read) ----
    const int mBase = m0 + warp_m * 32;
    const int nBase = n0 + warp_n * 64;
    const int r0 = lane >> 2;
    const int cpair = (lane & 3) * 2;
    #pragma unroll
    for (int mi = 0; mi < 2; ++mi) {
        #pragma unroll
        for (int ni = 0; ni < 8; ++ni) {
            float* p0 = out + (size_t)(mBase + mi * 16 + r0) * NDIM + nBase + ni * 8 + cpair;
            float* p1 = out + (size_t)(mBase + mi * 16 + r0 + 8) * NDIM + nBase + ni * 8 + cpair;
            __stcs(reinterpret_cast<float2*>(p0), make_float2(acc[mi][ni][0], acc[mi][ni][1]));
            __stcs(reinterpret_cast<float2*>(p1), make_float2(acc[mi][ni][2], acc[mi][ni][3]));
        }
    }
}

extern "C" void kernel_launch(void* const* d_in, const int* in_sizes, int n_in,
                              void* d_out, int out_size) {
    const float* x  = (const float*)d_in[0];
    const int* qw   = (const int*)d_in[1];
    const int* qz   = (const int*)d_in[2];
    const float* sc = (const float*)d_in[3];
    float* out      = (float*)d_out;

    cudaFuncSetAttribute(gemm_kernel, cudaFuncAttributeMaxDynamicSharedMemorySize, SMEM_TOTAL);

    prep_kernel<<<PREP_BLOCKS, 256>>>(x, qw, qz, sc);
    gemm_kernel<<<GRID_M * GRID_N, THREADS, SMEM_TOTAL>>>(out);
}

// round 16
// speedup vs baseline: 1.0780x; 1.0780x over previous
#include <cuda_runtime.h>
#include <cuda_fp16.h>
#include <cstdint>

// Shapes: x[4,1024,4096] f32, qweight[512,11008] i32 (8x4b along K),
// qzeros[32,1376] i32 (8x4b along N), scales[32,11008] f32, out[4096,11008] f32.
#define MDIM 4096
#define KDIM 4096
#define NDIM 11008

#define BM 128
#define BN 128
#define BK 64
#define STAGES 3
#define THREADS 256
#define NIT (KDIM / BK)          // 64
#define GRID_M (MDIM / BM)       // 32
#define GRID_N (NDIM / BN)       // 86

#define ROWB 128                                  // 128B rows, XOR swizzle
#define A_STAGE (BM * ROWB)                       // 16384
#define B_STAGE (BN * ROWB)                       // 16384
#define STAGE_BYTES (A_STAGE + B_STAGE)           // 32768
#define SMEM_TOTAL (STAGE_BYTES * STAGES)         // 98304  -> 2 CTAs/SM

#define CVT_BLOCKS (MDIM * KDIM / 8 / 256)        // 8192
#define DQ_BX (NDIM / 64)                         // 172
#define DQ_BY (KDIM / 64)                         // 64
#define PREP_BLOCKS (CVT_BLOCKS + DQ_BX * DQ_BY)  // 19200

// fp16 staging of A (x) and dequantized W^T (N-major, K contiguous)
__device__ __align__(16) __half g_xh[(size_t)MDIM * KDIM];   // 33.5 MB
__device__ __align__(16) __half g_wt[(size_t)NDIM * KDIM];   // 90.2 MB

// ---------------- merged prepass: x->fp16  +  dequant/transpose ----------------
__global__ void __launch_bounds__(256) prep_kernel(const float* __restrict__ x,
                                                   const int* __restrict__ qweight,
                                                   const int* __restrict__ qzeros,
                                                   const float* __restrict__ scales) {
    const int t = threadIdx.x;
    if (blockIdx.x < CVT_BLOCKS) {
        size_t idx = (size_t)blockIdx.x * 256 + t;
        const float4* xp = reinterpret_cast<const float4*>(x) + idx * 2;
        float4 a = xp[0], b = xp[1];
        __half2 h0 = __floats2half2_rn(a.x, a.y);
        __half2 h1 = __floats2half2_rn(a.z, a.w);
        __half2 h2 = __floats2half2_rn(b.x, b.y);
        __half2 h3 = __floats2half2_rn(b.z, b.w);
        uint4 o;
        o.x = *reinterpret_cast<uint32_t*>(&h0);
        o.y = *reinterpret_cast<uint32_t*>(&h1);
        o.z = *reinterpret_cast<uint32_t*>(&h2);
        o.w = *reinterpret_cast<uint32_t*>(&h3);
        reinterpret_cast<uint4*>(g_xh)[idx] = o;
        return;
    }
    __shared__ __align__(16) uint8_t tile[64 * 128];
    const int b = blockIdx.x - CVT_BLOCKS;
    const int n0 = (b % DQ_BX) * 64;
    const int by = b / DQ_BX;
    const int k0 = by * 64;
    const int kp0 = by * 8;
    const int g = k0 >> 7;

    const int nl = t & 63;
    const int n = n0 + nl;
    const int z = ((uint32_t)qzeros[g * (NDIM / 8) + (n >> 3)] >> ((n & 7) * 4)) & 0xF;
    const float s = scales[(size_t)g * NDIM + n];

    #pragma unroll
    for (int i = 0; i < 2; ++i) {
        int item = i * 256 + t;
        int kp = item >> 6;
        uint32_t q = (uint32_t)qweight[(size_t)(kp0 + kp) * NDIM + n];
        __half h[8];
        #pragma unroll
        for (int j = 0; j < 8; ++j) {
            int v = (q >> (4 * j)) & 0xF;
            h[j] = __float2half_rn((float)(v - z) * s);
        }
        int colb = (kp * 16) ^ ((nl & 7) << 4);
        *reinterpret_cast<uint4*>(tile + nl * 128 + colb) = *reinterpret_cast<uint4*>(h);
    }
    __syncthreads();
    #pragma unroll
    for (int i = 0; i < 8; ++i) {
        int idx = i * 256 + t;
        int row = idx >> 5, col = idx & 31;
        uint32_t v = *reinterpret_cast<uint32_t*>(tile + row * 128 + ((col * 4) ^ ((row & 7) << 4)));
        *reinterpret_cast<uint32_t*>(&g_wt[(size_t)(n0 + row) * KDIM + k0 + col * 2]) = v;
    }
}

// ---------------- PTX helpers ----------------
__device__ __forceinline__ void ldsm4(uint32_t* r, uint32_t addr) {
    asm volatile("ldmatrix.sync.aligned.m8n8.x4.shared.b16 {%0,%1,%2,%3}, [%4];"
                 : "=r"(r[0]), "=r"(r[1]), "=r"(r[2]), "=r"(r[3]) : "r"(addr));
}
__device__ __forceinline__ void mma16816(float* c, const uint32_t* a, uint32_t b0, uint32_t b1) {
    asm volatile("mma.sync.aligned.m16n8k16.row.col.f32.f16.f16.f32 "
                 "{%0,%1,%2,%3}, {%4,%5,%6,%7}, {%8,%9}, {%0,%1,%2,%3};"
                 : "+f"(c[0]), "+f"(c[1]), "+f"(c[2]), "+f"(c[3])
                 : "r"(a[0]), "r"(a[1]), "r"(a[2]), "r"(a[3]), "r"(b0), "r"(b1));
}
__device__ __forceinline__ void cp_async16(uint32_t dst, const void* src) {
    asm volatile("cp.async.cg.shared.global [%0], [%1], 16;" :: "r"(dst), "l"(src));
}
#define CP_COMMIT() asm volatile("cp.async.commit_group;" ::: "memory")
#define CP_WAIT(N)  asm volatile("cp.async.wait_group %0;" :: "n"(N) : "memory")

// ---------------- main GEMM: 128x128 tile, 2 CTAs/SM, barrier hidden in kh=3 ----------------
__global__ void __launch_bounds__(THREADS, 2) gemm_kernel(float* __restrict__ out) {
    extern __shared__ __align__(16) char smem[];
    const uint32_t smem_base = (uint32_t)__cvta_generic_to_shared(smem);

    const int t = threadIdx.x;
    const int wid = t >> 5;
    const int lane = t & 31;

    const int mtile = blockIdx.x & 31;          // mtile fastest: wave shares A fully + B slices in L2
    const int ntile = blockIdx.x >> 5;
    const int m0 = mtile * BM;
    const int n0 = ntile * BN;

    const int warp_m = wid & 3;                 // 4 slabs x 32 rows
    const int warp_n = wid >> 2;                // 2 slabs x 64 cols

    float acc[2][8][4];
    #pragma unroll
    for (int i = 0; i < 2; ++i)
        #pragma unroll
        for (int j = 0; j < 8; ++j)
            #pragma unroll
            for (int k = 0; k < 4; ++k) acc[i][j][k] = 0.f;

    // per-thread cp.async source/dest components
    const int ldRow = t >> 3;                   // 0..31 (row block step 32)
    const int ldCol = t & 7;                    // 16B chunk
    const uint32_t ldDstOff = ldRow * ROWB + ((ldCol * 16) ^ ((ldRow & 7) << 4));

    // rolling global source pointers (advance by BK per iter; issue targets it+2)
    const __half* srcA = g_xh + (size_t)(m0 + ldRow) * KDIM + ldCol * 8;
    const __half* srcB = g_wt + (size_t)(n0 + ldRow) * KDIM + ldCol * 8;

    auto issue_A = [&](uint32_t dstBase, const __half* src) {
        #pragma unroll
        for (int j = 0; j < 4; ++j)
            cp_async16(dstBase + j * 32 * ROWB, src + (size_t)(j * 32) * KDIM);
    };
    auto issue_B = [&](uint32_t dstBase, const __half* src) {
        #pragma unroll
        for (int j = 0; j < 4; ++j)
            cp_async16(dstBase + A_STAGE + j * 32 * ROWB, src + (size_t)(j * 32) * KDIM);
    };

    // prologue: stages 0 and 1 in flight
    issue_A(smem_base + ldDstOff, srcA);
    issue_B(smem_base + ldDstOff, srcB);
    CP_COMMIT();
    issue_A(smem_base + STAGE_BYTES + ldDstOff, srcA + BK);
    issue_B(smem_base + STAGE_BYTES + ldDstOff, srcB + BK);
    CP_COMMIT();
    srcA += 2 * BK;                              // now points at it+2 source
    srcB += 2 * BK;
    CP_WAIT(1);
    __syncthreads();

    const int rA = lane & 15;
    const int cA = (lane >> 4) * 16;
    const int swzA = (lane & 7) << 4;
    const int rB = ((lane >> 3) & 1) * 8 + (lane & 7);
    const int cB = (lane >> 4) * 16;
    const int swzB = (lane & 7) << 4;

    // warp-level smem row bases (stage-invariant parts)
    const uint32_t aRow0 = (warp_m * 32 + rA) * ROWB;
    const uint32_t bRow0 = (warp_n * 64 + rB) * ROWB;

    uint32_t afrag[2][2][4];     // double-buffered across kh
    uint32_t bfrag[2][2][4];     // slot0: np={0,1}, slot1: np={2,3}

    uint32_t consBase = smem_base;               // stage being consumed
    uint32_t prodBase = smem_base + 2 * STAGE_BYTES;   // stage being filled (it+2)

    // preload iter0 kh=0 frags from stage 0 (ready)
    #pragma unroll
    for (int mi = 0; mi < 2; ++mi)
        ldsm4(afrag[0][mi], consBase + aRow0 + mi * 16 * ROWB + (cA ^ swzA));
    #pragma unroll
    for (int np = 0; np < 2; ++np)
        ldsm4(bfrag[0][np], consBase + A_STAGE + bRow0 + np * 16 * ROWB + (cB ^ swzB));

    #pragma unroll 1
    for (int it = 0; it < NIT; ++it) {
        const uint32_t aBase = consBase;
        const uint32_t bBase = consBase + A_STAGE;
        const uint32_t consNext = (consBase == smem_base + 2 * STAGE_BYTES)
                                      ? smem_base : consBase + STAGE_BYTES;
        const bool more = (it + 2 < NIT);

        #pragma unroll
        for (int kh = 0; kh < 4; ++kh) {
            const int cur = kh & 1, nxt = cur ^ 1;
            const uint32_t kcol = kh * 32;
            const bool last = (kh == 3);
            // bases/col for the "next" (kh+1 or next-iter kh=0) fragment loads
            const uint32_t aNB = last ? consNext : aBase;
            const uint32_t bNB = last ? (consNext + A_STAGE) : bBase;
            const uint32_t kcolN = last ? 0 : (kcol + 32);

            // B slot1 (np 2,3) for this kh — last smem read of current stage at kh=3
            #pragma unroll
            for (int np = 0; np < 2; ++np)
                ldsm4(bfrag[1][np], bBase + bRow0 + (np + 2) * 16 * ROWB + ((kcol + cB) ^ swzB));

            if (last) {          // stage it+1 ready; all reads of recycled buffer done
                CP_WAIT(1);
                __syncthreads();
            }

            // A frags for next kh / next iter (from next stage when kh=3)
            #pragma unroll
            for (int mi = 0; mi < 2; ++mi)
                ldsm4(afrag[nxt][mi], aNB + aRow0 + mi * 16 * ROWB + ((kcolN + cA) ^ swzA));

            // interleave next-next stage global loads into MMA-rich region
            if (kh == 0 && more) issue_A(prodBase + ldDstOff, srcA);
            if (kh == 1) { if (more) issue_B(prodBase + ldDstOff, srcB); CP_COMMIT(); }

            // MMA pair 0 (np 0,1)
            #pragma unroll
            for (int np = 0; np < 2; ++np)
                #pragma unroll
                for (int mi = 0; mi < 2; ++mi) {
                    mma16816(acc[mi][2 * np],     afrag[cur][mi], bfrag[0][np][0], bfrag[0][np][2]);
                    mma16816(acc[mi][2 * np + 1], afrag[cur][mi], bfrag[0][np][1], bfrag[0][np][3]);
                }
            // B slot0 (np 0,1) for next kh / next iter, hidden under pair-1 MMAs
            #pragma unroll
            for (int np = 0; np < 2; ++np)
                ldsm4(bfrag[0][np], bNB + bRow0 + np * 16 * ROWB + ((kcolN + cB) ^ swzB));
            // MMA pair 1 (np 2,3)
            #pragma unroll
            for (int np = 0; np < 2; ++np)
                #pragma unroll
                for (int mi = 0; mi < 2; ++mi) {
                    mma16816(acc[mi][4 + 2 * np],     afrag[cur][mi], bfrag[1][np][0], bfrag[1][np][2]);
                    mma16816(acc[mi][4 + 2 * np + 1], afrag[cur][mi], bfrag[1][np][1], bfrag[1][np][3]);
                }
        }

        // rotate stages, advance sources
        consBase = consNext;
        prodBase += STAGE_BYTES;
        if (prodBase == smem_base + 3 * STAGE_BYTES) prodBase = smem_base;
        srcA += BK;
        srcB += BK;
    }

    // ---- epilogue: streaming float2 stores (out is never re-read) ----
    const int mBase = m0 + warp_m * 32;
    const int nBase = n0 + warp_n * 64;
    const int r0 = lane >> 2;
    const int cpair = (lane & 3) * 2;
    #pragma unroll
    for (int mi = 0; mi < 2; ++mi) {
        #pragma unroll
        for (int ni = 0; ni < 8; ++ni) {
            float* p0 = out + (size_t)(mBase + mi * 16 + r0) * NDIM + nBase + ni * 8 + cpair;
            float* p1 = out + (size_t)(mBase + mi * 16 + r0 + 8) * NDIM + nBase + ni * 8 + cpair;
            __stcs(reinterpret_cast<float2*>(p0), make_float2(acc[mi][ni][0], acc[mi][ni][1]));
            __stcs(reinterpret_cast<float2*>(p1), make_float2(acc[mi][ni][2], acc[mi][ni][3]));
        }
    }
}

extern "C" void kernel_launch(void* const* d_in, const int* in_sizes, int n_in,
                              void* d_out, int out_size) {
    const float* x  = (const float*)d_in[0];
    const int* qw   = (const int*)d_in[1];
    const int* qz   = (const int*)d_in[2];
    const float* sc = (const float*)d_in[3];
    float* out      = (float*)d_out;

    cudaFuncSetAttribute(gemm_kernel, cudaFuncAttributeMaxDynamicSharedMemorySize, SMEM_TOTAL);

    prep_kernel<<<PREP_BLOCKS, 256>>>(x, qw, qz, sc);
    gemm_kernel<<<GRID_M * GRID_N, THREADS, SMEM_TOTAL>>>(out);
}